// round 5
// baseline (speedup 1.0000x reference)
#include <cuda_runtime.h>

// ReactantCentreIdentify — fused segment-mean-gate-concat.
//   node_rep      [N=400000, D=300] f32
//   batch         [N] i32, SORTED ascending in [0, B)
//   primary_label [N] i32 in {-1, 0}
//   out           [N, 600] f32 = [node_rep | cond_pool[batch]]
//
// Two launches (graph-captured together):
//  1) seg_kernel: grid-stride over batch, writes seg_start[g] = lower_bound(g)
//     for g in [0, B] into device-global scratch. Removes the per-CTA serial
//     binary search (and its kernel-start DRAM idle bubble) from the hot kernel.
//  2) main kernel: one CTA per graph (grid=4096), block (75,4)=300 threads,
//     regs<=32 -> 6 CTAs/SM, 60 warps (the proven bandwidth config).
//     Pass 1 streams rows with L2 prefetch 3 iters ahead: copy left half
//     (evict-first stores), accumulate condition rows in registers with fixed
//     column ownership. Cross-lane reduce in shared, gate on last-node label,
//     scale by 1/max(cnt,1). Pass 2 broadcasts pooled vector into right half.

#define D4   75          // D/4 float4 per input row
#define OUT4 150         // 2D/4 float4 per output row
#define BY   4           // row lanes per block
#define PF   3           // prefetch distance in loop iterations (PF*BY rows)
#define NGRAPH 4096

__device__ int g_seg_start[NGRAPH + 1];

__global__ void seg_kernel(const int* __restrict__ batch, int n)
{
    int i = blockIdx.x * blockDim.x + threadIdx.x;
    if (i >= n) return;
    int b  = batch[i];
    int bp = (i == 0) ? -1 : batch[i - 1];
    // fill boundaries for graphs starting at row i (handles empty graphs)
    for (int g = bp + 1; g <= b; g++) g_seg_start[g] = i;
    if (i == n - 1) {
        for (int g = b + 1; g <= NGRAPH; g++) g_seg_start[g] = n;
    }
}

__global__ __launch_bounds__(D4 * BY, 6)
void reactant_centre_kernel(const float4* __restrict__ x4,     // [N, 75]
                            const int*    __restrict__ label,  // [N]
                            float4*       __restrict__ out4)   // [N, 150]
{
    const int g   = blockIdx.x;
    const int c4  = threadIdx.x;   // 0..74  (float4 column)
    const int ry  = threadIdx.y;   // 0..3   (row lane)
    const int tid = ry * D4 + c4;

    __shared__ int    s_se[2];
    __shared__ float4 s_acc[BY][D4];
    __shared__ int    s_cnt[BY];
    __shared__ float4 s_pool[D4];

    if (tid < 2) s_se[tid] = g_seg_start[g + tid];
    __syncthreads();
    const int s = s_se[0];
    const int e = s_se[1];

    const bool do_pf = ((c4 & 7) == 0);   // one prefetcher per 128B line

    // ---- Pass 1: copy left half + accumulate condition rows ----
    float4 acc = make_float4(0.f, 0.f, 0.f, 0.f);
    int cnt = 0;
    for (int r = s + ry; r < e; r += BY) {
        if (do_pf) {
            int rp = r + PF * BY;
            if (rp > e - 1) rp = e - 1;
            const float4* pp = x4 + (long)rp * D4 + c4;
            asm volatile("prefetch.global.L2 [%0];" :: "l"(pp));
        }
        float4 v = x4[(long)r * D4 + c4];
        int   l = label[r];
        __stcs(out4 + (long)r * OUT4 + c4, v);   // evict-first: write-once data
        if (l == -1) {
            acc.x += v.x; acc.y += v.y; acc.z += v.z; acc.w += v.w;
            cnt++;
        }
    }
    s_acc[ry][c4] = acc;
    if (c4 == 0) s_cnt[ry] = cnt;
    __syncthreads();

    // Gate: pool only if the LAST node of the graph is a condition node.
    const bool flag = (e > s) && (label[e - 1] == -1);

    if (ry == 0) {
        float4 a = s_acc[0][c4];
        float4 b = s_acc[1][c4];
        float4 c = s_acc[2][c4];
        float4 d = s_acc[3][c4];
        float tc  = (float)(s_cnt[0] + s_cnt[1] + s_cnt[2] + s_cnt[3]);
        float inv = flag ? (1.0f / fmaxf(tc, 1.0f)) : 0.0f;
        s_pool[c4] = make_float4((a.x + b.x + c.x + d.x) * inv,
                                 (a.y + b.y + c.y + d.y) * inv,
                                 (a.z + b.z + c.z + d.z) * inv,
                                 (a.w + b.w + c.w + d.w) * inv);
    }
    __syncthreads();

    // ---- Pass 2: broadcast pooled vector into right half ----
    const float4 p = s_pool[c4];
    for (int r = s + ry; r < e; r += BY) {
        __stcs(out4 + (long)r * OUT4 + D4 + c4, p);
    }
}

extern "C" void kernel_launch(void* const* d_in, const int* in_sizes, int n_in,
                              void* d_out, int out_size)
{
    const float* node_rep = (const float*)d_in[0];
    const int*   batch    = (const int*)d_in[1];
    const int*   label    = (const int*)d_in[2];
    (void)n_in; (void)out_size;

    const int n = in_sizes[1];        // N from batch array

    seg_kernel<<<(n + 255) / 256, 256>>>(batch, n);

    dim3 block(D4, BY);               // 75 x 4 = 300 threads
    reactant_centre_kernel<<<NGRAPH, block>>>((const float4*)node_rep, label,
                                              (float4*)d_out);
}

// round 7
// speedup vs baseline: 1.0558x; 1.0558x over previous
#include <cuda_runtime.h>

// ReactantCentreIdentify — fused segment-mean-gate-concat.
//   node_rep      [N=400000, D=300] f32
//   batch         [N] i32, SORTED ascending in [0, B=4096)
//   primary_label [N] i32 in {-1, 0}
//   out           [N, 600] f32 = [node_rep | cond_pool[batch]]
//
// One CTA per graph (grid=4096). Block (75,6)=450 threads = 15 warps;
// 4 CTAs/SM -> 60 warps (same bandwidth config as the proven 73.7% DRAM
// kernel, but smaller per-graph quantum -> shorter end-of-kernel drain).
// batch sorted => graph g is rows [s,e), found by a windowed binary search
// (start positions are Binomial(N, g/B), sigma<=316; +/-4096 window is >12
// sigma). Pass 1 streams rows with L2 prefetch 12 rows ahead: copy left
// half, accumulate condition rows in registers (fixed column ownership).
// Cross-lane reduce in shared, gate on last-node label, scale 1/max(cnt,1).
// Pass 2 broadcasts the pooled vector into the right half.

#define D4   75          // D/4 float4 per input row
#define OUT4 150         // 2D/4 float4 per output row
#define BY   6           // row lanes per block
#define PFR  12          // prefetch distance in rows
#define NGRAPH 4096
#define SWIN 4096        // binary-search half-window around expected start

__global__ __launch_bounds__(D4 * BY, 4)
void reactant_centre_kernel(const float4* __restrict__ x4,     // [N, 75]
                            const int*    __restrict__ batch,  // [N]
                            const int*    __restrict__ label,  // [N]
                            float4*       __restrict__ out4,   // [N, 150]
                            int n)
{
    const int g   = blockIdx.x;
    const int c4  = threadIdx.x;   // 0..74  (float4 column)
    const int ry  = threadIdx.y;   // 0..BY-1 (row lane)
    const int tid = ry * D4 + c4;

    __shared__ int    s_se[2];
    __shared__ float4 s_acc[BY][D4];
    __shared__ int    s_cnt[BY];
    __shared__ float4 s_pool[D4];

    // lower_bound for g and g+1, windowed around the expected position.
    if (tid < 2) {
        int target = g + tid;
        long est = ((long)target * n) / NGRAPH;
        int lo = (int)(est - SWIN); if (lo < 0) lo = 0;
        int hi = (int)(est + SWIN); if (hi > n) hi = n;
        // widen if window assumption ever fails (paranoia; costs nothing when true)
        if (lo > 0 && batch[lo] >= target) lo = 0;
        if (hi < n && batch[hi - 1] < target) hi = n;
        while (lo < hi) {
            int mid = (lo + hi) >> 1;
            if (batch[mid] < target) lo = mid + 1; else hi = mid;
        }
        s_se[tid] = lo;
    }
    __syncthreads();
    const int s = s_se[0];
    const int e = s_se[1];

    const bool do_pf = ((c4 & 7) == 0);   // one prefetcher per 128B line

    // ---- Pass 1: copy left half + accumulate condition rows ----
    float4 acc = make_float4(0.f, 0.f, 0.f, 0.f);
    int cnt = 0;
    for (int r = s + ry; r < e; r += BY) {
        if (do_pf) {
            int rp = r + PFR;
            if (rp > e - 1) rp = e - 1;
            const float4* pp = x4 + (long)rp * D4 + c4;
            asm volatile("prefetch.global.L2 [%0];" :: "l"(pp));
        }
        float4 v = x4[(long)r * D4 + c4];
        int   l = label[r];
        out4[(long)r * OUT4 + c4] = v;
        if (l == -1) {
            acc.x += v.x; acc.y += v.y; acc.z += v.z; acc.w += v.w;
            cnt++;
        }
    }
    s_acc[ry][c4] = acc;
    if (c4 == 0) s_cnt[ry] = cnt;
    __syncthreads();

    // Gate: pool only if the LAST node of the graph is a condition node.
    const bool flag = (e > s) && (label[e - 1] == -1);

    if (ry == 0) {
        float4 t = s_acc[0][c4];
        int tc_i = s_cnt[0];
        #pragma unroll
        for (int k = 1; k < BY; k++) {
            float4 a = s_acc[k][c4];
            t.x += a.x; t.y += a.y; t.z += a.z; t.w += a.w;
            tc_i += s_cnt[k];
        }
        float inv = flag ? (1.0f / fmaxf((float)tc_i, 1.0f)) : 0.0f;
        s_pool[c4] = make_float4(t.x * inv, t.y * inv, t.z * inv, t.w * inv);
    }
    __syncthreads();

    // ---- Pass 2: broadcast pooled vector into right half ----
    const float4 p = s_pool[c4];
    for (int r = s + ry; r < e; r += BY) {
        out4[(long)r * OUT4 + D4 + c4] = p;
    }
}

extern "C" void kernel_launch(void* const* d_in, const int* in_sizes, int n_in,
                              void* d_out, int out_size)
{
    const float* node_rep = (const float*)d_in[0];
    const int*   batch    = (const int*)d_in[1];
    const int*   label    = (const int*)d_in[2];
    (void)n_in; (void)out_size;

    const int n = in_sizes[1];        // N from batch array

    dim3 block(D4, BY);               // 75 x 6 = 450 threads
    reactant_centre_kernel<<<NGRAPH, block>>>((const float4*)node_rep, batch,
                                              label, (float4*)d_out, n);
}